// round 14
// baseline (speedup 1.0000x reference)
#include <cuda_runtime.h>
#include <cuda_fp16.h>
#include <cstdint>

#define M_TOK 8192
#define N_OUT 4096
#define K_IN  4096

#define BM 128
#define BN 128
#define BK 64
#define NCHUNK (K_IN / BK)        // 64
#define NSTAGE 3
#define T_BYTES (128 * BK * 2)    // 16384 per tile
#define STAGE_BYTES (2 * T_BYTES) // A + B = 32768
#define SMEM_TOTAL (NSTAGE * STAGE_BYTES)   // 98304 -> 2 CTAs/SM

#define NTHREADS 128              // 4 warps, each owns a 64x64 warp tile

#define GRID_M (M_TOK / BM)       // 64
#define GRID_N (N_OUT / BN)       // 32
#define GROUP_M 8

#define XBLOCKS 32768             // pack grid split point (x part)
#define WBLOCKS 16384

// -------------------- static device scratch (~100 MB) --------------------
__device__ __half g_ax[(size_t)M_TOK * K_IN];  // 67 MB  fp16(x)
__device__ __half g_bw[(size_t)N_OUT * K_IN];  // 33.5 MB fp16(W + s*B@A)

// -------------------- helpers --------------------
static __device__ __forceinline__ uint32_t s2u(const void* p) {
    uint32_t a;
    asm("{ .reg .u64 t; cvta.to.shared.u64 t, %1; cvt.u32.u64 %0, t; }"
        : "=r"(a) : "l"(p));
    return a;
}
#define SWZ(o) ((o) ^ (((o) >> 3) & 0x70))

static __device__ __forceinline__ void cp16(uint32_t dst, const void* src) {
    asm volatile("cp.async.cg.shared.global [%0], [%1], 16;" :: "r"(dst), "l"(src));
}
static __device__ __forceinline__ void cp_commit() {
    asm volatile("cp.async.commit_group;" ::: "memory");
}

static __device__ __forceinline__ void ldmx4(uint32_t* r, uint32_t addr) {
    asm volatile("ldmatrix.sync.aligned.m8n8.x4.shared.b16 {%0,%1,%2,%3}, [%4];"
                 : "=r"(r[0]), "=r"(r[1]), "=r"(r[2]), "=r"(r[3]) : "r"(addr));
}
static __device__ __forceinline__ void mma16816(float* c, const uint32_t* a,
                                                uint32_t b0, uint32_t b1) {
    asm volatile(
        "mma.sync.aligned.m16n8k16.row.col.f32.f16.f16.f32 "
        "{%0,%1,%2,%3}, {%4,%5,%6,%7}, {%8,%9}, {%0,%1,%2,%3};"
        : "+f"(c[0]), "+f"(c[1]), "+f"(c[2]), "+f"(c[3])
        : "r"(a[0]), "r"(a[1]), "r"(a[2]), "r"(a[3]), "r"(b0), "r"(b1));
}

// ---------- merged prepass: x -> fp16, and Wf = W + s*B@A -> fp16 ----------
__global__ __launch_bounds__(256) void pack_all(
    const float* __restrict__ x, const float* __restrict__ W,
    const float* __restrict__ B, const float* __restrict__ A,
    const float* __restrict__ sp)
{
    if (blockIdx.x < XBLOCKS) {
        size_t i = ((size_t)blockIdx.x * 256 + threadIdx.x) * 4;
        float4 v = *(const float4*)(x + i);
        ushort4 h;
        h.x = __half_as_ushort(__float2half_rn(v.x));
        h.y = __half_as_ushort(__float2half_rn(v.y));
        h.z = __half_as_ushort(__float2half_rn(v.z));
        h.w = __half_as_ushort(__float2half_rn(v.w));
        *(ushort4*)((unsigned short*)g_ax + i) = h;
    } else {
        size_t idx4 = (size_t)(blockIdx.x - XBLOCKS) * 256 + threadIdx.x;
        int row = (int)(idx4 >> 10);
        int col = (int)(idx4 & 1023) * 4;
        float s = *sp;

        float4 w = *(const float4*)(W + (size_t)row * K_IN + col);
        float4 acc = make_float4(0.f, 0.f, 0.f, 0.f);
        const float* brow = B + (size_t)row * 16;
        #pragma unroll
        for (int r = 0; r < 16; r++) {
            float b = brow[r];
            float4 a = *(const float4*)(A + (size_t)r * K_IN + col);
            acc.x += b * a.x; acc.y += b * a.y; acc.z += b * a.z; acc.w += b * a.w;
        }
        w.x += s * acc.x; w.y += s * acc.y; w.z += s * acc.z; w.w += s * acc.w;

        ushort4 h;
        h.x = __half_as_ushort(__float2half_rn(w.x));
        h.y = __half_as_ushort(__float2half_rn(w.y));
        h.z = __half_as_ushort(__float2half_rn(w.z));
        h.w = __half_as_ushort(__float2half_rn(w.w));
        *(ushort4*)((unsigned short*)g_bw + (size_t)row * K_IN + col) = h;
    }
}

// -------------------- main GEMM: out = x_h @ w_h^T + bias --------------------
__global__ __launch_bounds__(NTHREADS, 2) void lora_mma_gemm(
    const float* __restrict__ bias, float* __restrict__ out)
{
    extern __shared__ __align__(1024) char smem[];
    const uint32_t sb = s2u(smem);
    const int tid  = threadIdx.x;
    const int lane = tid & 31;
    const int wid  = tid >> 5;
    const int warp_m = wid & 1;       // 2 warps in M -> 64 rows each
    const int warp_n = wid >> 1;      // 2 warps in N -> 64 cols each

    const int bid   = blockIdx.x;
    const int group = bid / (GROUP_M * GRID_N);
    const int inner = bid % (GROUP_M * GRID_N);
    const int bm    = (group * GROUP_M + (inner % GROUP_M)) * BM;
    const int bn    = (inner / GROUP_M) * BN;

    const __half* Ag = g_ax + (size_t)bm * K_IN;
    const __half* Bg = g_bw + (size_t)bn * K_IN;

    const int lrow = lane & 15;
    const int lkb  = (lane >> 4) * 16;

    float c[4][8][4];
    #pragma unroll
    for (int i = 0; i < 4; i++)
        #pragma unroll
        for (int j = 0; j < 8; j++)
            #pragma unroll
            for (int q = 0; q < 4; q++) c[i][j][q] = 0.f;

    // stage layout: [A 16K | B 16K]
    auto load_stage = [&](int ch, int st) {
        const uint32_t ab = sb + st * STAGE_BYTES;
        const uint32_t bb = ab + T_BYTES;
        const int k0 = ch * BK;
        #pragma unroll
        for (int i = 0; i < 8; i++) {       // 1024 granules of 16B per tile
            int G = tid + i * NTHREADS;
            int r = G >> 3, g = G & 7;
            uint32_t so = SWZ((uint32_t)(r * 128 + g * 16));
            cp16(ab + so, Ag + (size_t)r * K_IN + k0 + g * 8);
            cp16(bb + so, Bg + (size_t)r * K_IN + k0 + g * 8);
        }
        cp_commit();
    };

    #pragma unroll
    for (int s = 0; s < NSTAGE - 1; s++) load_stage(s, s);

    for (int ch = 0; ch < NCHUNK; ch++) {
        asm volatile("cp.async.wait_group 1;" ::: "memory");
        __syncthreads();

        // load stage ch+2 into slot (ch+2)%3 — consumed in iter ch-1, pre-barrier
        if (ch + NSTAGE - 1 < NCHUNK) {
            const int nc = ch + NSTAGE - 1;
            load_stage(nc, nc % NSTAGE);
        } else cp_commit();   // keep group accounting balanced

        const int st = ch % NSTAGE;
        const uint32_t ab = sb + st * STAGE_BYTES;
        const uint32_t bb = ab + T_BYTES;

        #pragma unroll
        for (int ks = 0; ks < 4; ks++) {
            uint32_t ra[4][4], rb[4][4];
            #pragma unroll
            for (int mf = 0; mf < 4; mf++)
                ldmx4(ra[mf], ab + SWZ((uint32_t)((warp_m * 64 + mf * 16 + lrow) * 128
                                                  + ks * 32 + lkb)));
            #pragma unroll
            for (int j = 0; j < 4; j++)
                ldmx4(rb[j], bb + SWZ((uint32_t)((warp_n * 64 + j * 16 + lrow) * 128
                                                 + ks * 32 + lkb)));
            #pragma unroll
            for (int mf = 0; mf < 4; mf++)
                #pragma unroll
                for (int nf = 0; nf < 8; nf++)
                    mma16816(c[mf][nf], ra[mf],
                             rb[nf >> 1][nf & 1], rb[nf >> 1][(nf & 1) + 2]);
        }
    }

    // -------- epilogue: regs + bias -> gmem --------
    const int tq = lane >> 2, t4 = lane & 3;
    float2 bv[8];
    #pragma unroll
    for (int nf = 0; nf < 8; nf++)
        bv[nf] = *(const float2*)(bias + bn + warp_n * 64 + nf * 8 + t4 * 2);

    #pragma unroll
    for (int mf = 0; mf < 4; mf++) {
        const int r0 = bm + warp_m * 64 + mf * 16 + tq;
        float* o0 = out + (size_t)r0 * N_OUT + bn + warp_n * 64;
        float* o1 = o0 + 8 * N_OUT;
        #pragma unroll
        for (int nf = 0; nf < 8; nf++) {
            const int colo = nf * 8 + t4 * 2;
            *(float2*)(o0 + colo) = make_float2(c[mf][nf][0] + bv[nf].x,
                                                c[mf][nf][1] + bv[nf].y);
            *(float2*)(o1 + colo) = make_float2(c[mf][nf][2] + bv[nf].x,
                                                c[mf][nf][3] + bv[nf].y);
        }
    }
}

// -------------------- launch --------------------
extern "C" void kernel_launch(void* const* d_in, const int* in_sizes, int n_in,
                              void* d_out, int out_size)
{
    (void)in_sizes; (void)n_in; (void)out_size;
    const float* x     = (const float*)d_in[0];
    const float* W     = (const float*)d_in[1];
    const float* bias  = (const float*)d_in[2];
    const float* loraB = (const float*)d_in[3];
    const float* loraA = (const float*)d_in[4];
    const float* scale = (const float*)d_in[5];
    float* out = (float*)d_out;

    pack_all<<<XBLOCKS + WBLOCKS, 256>>>(x, W, loraB, loraA, scale);

    cudaFuncSetAttribute(lora_mma_gemm,
                         cudaFuncAttributeMaxDynamicSharedMemorySize, SMEM_TOTAL);
    lora_mma_gemm<<<GRID_M * GRID_N, NTHREADS, SMEM_TOTAL>>>(bias, out);
}

// round 15
// speedup vs baseline: 1.0033x; 1.0033x over previous
#include <cuda_runtime.h>
#include <cuda_fp16.h>
#include <cstdint>

#define M_TOK 8192
#define N_OUT 4096
#define K_IN  4096

#define BM 128
#define BN 128
#define BK 64
#define NCHUNK (K_IN / BK)        // 64
#define NSTAGE 3
#define T_BYTES (128 * BK * 2)    // 16384 per tile
#define STAGE_BYTES (2 * T_BYTES) // A + B = 32768
#define SMEM_TOTAL (NSTAGE * STAGE_BYTES)   // 98304 -> 2 CTAs/SM

#define NTHREADS 128              // 4 warps, each owns a 64x64 warp tile

#define GRID_M (M_TOK / BM)       // 64
#define GRID_N (N_OUT / BN)       // 32
#define GROUP_M 8

// -------------------- static device scratch (~100 MB) --------------------
__device__ __half g_ax[(size_t)M_TOK * K_IN];  // 67 MB  fp16(x)
__device__ __half g_bw[(size_t)N_OUT * K_IN];  // 33.5 MB fp16(W + s*B@A)

// -------------------- helpers --------------------
static __device__ __forceinline__ uint32_t s2u(const void* p) {
    uint32_t a;
    asm("{ .reg .u64 t; cvta.to.shared.u64 t, %1; cvt.u32.u64 %0, t; }"
        : "=r"(a) : "l"(p));
    return a;
}
#define SWZ(o) ((o) ^ (((o) >> 3) & 0x70))

static __device__ __forceinline__ void cp16(uint32_t dst, const void* src) {
    asm volatile("cp.async.cg.shared.global [%0], [%1], 16;" :: "r"(dst), "l"(src));
}
static __device__ __forceinline__ void cp_commit() {
    asm volatile("cp.async.commit_group;" ::: "memory");
}

static __device__ __forceinline__ void ldmx4(uint32_t* r, uint32_t addr) {
    asm volatile("ldmatrix.sync.aligned.m8n8.x4.shared.b16 {%0,%1,%2,%3}, [%4];"
                 : "=r"(r[0]), "=r"(r[1]), "=r"(r[2]), "=r"(r[3]) : "r"(addr));
}
static __device__ __forceinline__ void mma16816(float* c, const uint32_t* a,
                                                uint32_t b0, uint32_t b1) {
    asm volatile(
        "mma.sync.aligned.m16n8k16.row.col.f32.f16.f16.f32 "
        "{%0,%1,%2,%3}, {%4,%5,%6,%7}, {%8,%9}, {%0,%1,%2,%3};"
        : "+f"(c[0]), "+f"(c[1]), "+f"(c[2]), "+f"(c[3])
        : "r"(a[0]), "r"(a[1]), "r"(a[2]), "r"(a[3]), "r"(b0), "r"(b1));
}

// ---------- prepass 1: x -> g_ax (single fp16 plane) ----------
__global__ __launch_bounds__(256) void pack_x(const float* __restrict__ x) {
    size_t i = ((size_t)blockIdx.x * 256 + threadIdx.x) * 4;
    float4 v = *(const float4*)(x + i);
    ushort4 h;
    h.x = __half_as_ushort(__float2half_rn(v.x));
    h.y = __half_as_ushort(__float2half_rn(v.y));
    h.z = __half_as_ushort(__float2half_rn(v.z));
    h.w = __half_as_ushort(__float2half_rn(v.w));
    *(ushort4*)((unsigned short*)g_ax + i) = h;
}

// ---------- prepass 2: Wf = W + s*B@A -> g_bw single fp16 plane ----------
__global__ __launch_bounds__(256) void pack_w(
    const float* __restrict__ W, const float* __restrict__ B,
    const float* __restrict__ A, const float* __restrict__ sp)
{
    size_t idx4 = (size_t)blockIdx.x * 256 + threadIdx.x;
    int row = (int)(idx4 >> 10);
    int col = (int)(idx4 & 1023) * 4;
    float s = *sp;

    float4 w = *(const float4*)(W + (size_t)row * K_IN + col);
    float4 acc = make_float4(0.f, 0.f, 0.f, 0.f);
    const float* brow = B + (size_t)row * 16;
    #pragma unroll
    for (int r = 0; r < 16; r++) {
        float b = brow[r];
        float4 a = *(const float4*)(A + (size_t)r * K_IN + col);
        acc.x += b * a.x; acc.y += b * a.y; acc.z += b * a.z; acc.w += b * a.w;
    }
    w.x += s * acc.x; w.y += s * acc.y; w.z += s * acc.z; w.w += s * acc.w;

    ushort4 h;
    h.x = __half_as_ushort(__float2half_rn(w.x));
    h.y = __half_as_ushort(__float2half_rn(w.y));
    h.z = __half_as_ushort(__float2half_rn(w.z));
    h.w = __half_as_ushort(__float2half_rn(w.w));
    *(ushort4*)((unsigned short*)g_bw + (size_t)row * K_IN + col) = h;
}

// -------------------- main GEMM: out = x_h @ w_h^T + bias --------------------
__global__ __launch_bounds__(NTHREADS, 2) void lora_mma_gemm(
    const float* __restrict__ bias, float* __restrict__ out)
{
    extern __shared__ __align__(1024) char smem[];
    const uint32_t sb = s2u(smem);
    const int tid  = threadIdx.x;
    const int lane = tid & 31;
    const int wid  = tid >> 5;
    const int warp_m = wid & 1;       // 2 warps in M -> 64 rows each
    const int warp_n = wid >> 1;      // 2 warps in N -> 64 cols each

    const int bid   = blockIdx.x;
    const int group = bid / (GROUP_M * GRID_N);
    const int inner = bid % (GROUP_M * GRID_N);
    const int bm    = (group * GROUP_M + (inner % GROUP_M)) * BM;
    const int bn    = (inner / GROUP_M) * BN;

    const __half* Ag = g_ax + (size_t)bm * K_IN;
    const __half* Bg = g_bw + (size_t)bn * K_IN;

    const int lrow = lane & 15;
    const int lkb  = (lane >> 4) * 16;

    float c[4][8][4];
    #pragma unroll
    for (int i = 0; i < 4; i++)
        #pragma unroll
        for (int j = 0; j < 8; j++)
            #pragma unroll
            for (int q = 0; q < 4; q++) c[i][j][q] = 0.f;

    // stage layout: [A 16K | B 16K]
    auto load_stage = [&](int ch, int st) {
        const uint32_t ab = sb + st * STAGE_BYTES;
        const uint32_t bb = ab + T_BYTES;
        const int k0 = ch * BK;
        #pragma unroll
        for (int i = 0; i < 8; i++) {       // 1024 granules of 16B per tile
            int G = tid + i * NTHREADS;
            int r = G >> 3, g = G & 7;
            uint32_t so = SWZ((uint32_t)(r * 128 + g * 16));
            cp16(ab + so, Ag + (size_t)r * K_IN + k0 + g * 8);
            cp16(bb + so, Bg + (size_t)r * K_IN + k0 + g * 8);
        }
        cp_commit();
    };

    #pragma unroll
    for (int s = 0; s < NSTAGE - 1; s++) load_stage(s, s);

    for (int ch = 0; ch < NCHUNK; ch++) {
        asm volatile("cp.async.wait_group 1;" ::: "memory");
        __syncthreads();

        // load stage ch+2 into slot (ch+2)%3 — consumed in iter ch-1, pre-barrier
        if (ch + NSTAGE - 1 < NCHUNK) {
            const int nc = ch + NSTAGE - 1;
            load_stage(nc, nc % NSTAGE);
        } else cp_commit();   // keep group accounting balanced

        const int st = ch % NSTAGE;
        const uint32_t ab = sb + st * STAGE_BYTES;
        const uint32_t bb = ab + T_BYTES;

        // double-buffered fragments: load ks+1 while issuing MMAs for ks
        uint32_t ra[2][4][4], rb[2][4][4];

        auto ldfrag = [&](int ks, int buf) {
            #pragma unroll
            for (int mf = 0; mf < 4; mf++)
                ldmx4(ra[buf][mf],
                      ab + SWZ((uint32_t)((warp_m * 64 + mf * 16 + lrow) * 128
                                          + ks * 32 + lkb)));
            #pragma unroll
            for (int j = 0; j < 4; j++)
                ldmx4(rb[buf][j],
                      bb + SWZ((uint32_t)((warp_n * 64 + j * 16 + lrow) * 128
                                          + ks * 32 + lkb)));
        };

        ldfrag(0, 0);
        #pragma unroll
        for (int ks = 0; ks < 4; ks++) {
            const int cur = ks & 1;
            if (ks < 3) ldfrag(ks + 1, cur ^ 1);
            #pragma unroll
            for (int mf = 0; mf < 4; mf++)
                #pragma unroll
                for (int nf = 0; nf < 8; nf++)
                    mma16816(c[mf][nf], ra[cur][mf],
                             rb[cur][nf >> 1][nf & 1], rb[cur][nf >> 1][(nf & 1) + 2]);
        }
    }

    // -------- epilogue: regs + bias -> gmem --------
    const int tq = lane >> 2, t4 = lane & 3;
    float2 bv[8];
    #pragma unroll
    for (int nf = 0; nf < 8; nf++)
        bv[nf] = *(const float2*)(bias + bn + warp_n * 64 + nf * 8 + t4 * 2);

    #pragma unroll
    for (int mf = 0; mf < 4; mf++) {
        const int r0 = bm + warp_m * 64 + mf * 16 + tq;
        float* o0 = out + (size_t)r0 * N_OUT + bn + warp_n * 64;
        float* o1 = o0 + 8 * N_OUT;
        #pragma unroll
        for (int nf = 0; nf < 8; nf++) {
            const int colo = nf * 8 + t4 * 2;
            *(float2*)(o0 + colo) = make_float2(c[mf][nf][0] + bv[nf].x,
                                                c[mf][nf][1] + bv[nf].y);
            *(float2*)(o1 + colo) = make_float2(c[mf][nf][2] + bv[nf].x,
                                                c[mf][nf][3] + bv[nf].y);
        }
    }
}

// -------------------- launch --------------------
extern "C" void kernel_launch(void* const* d_in, const int* in_sizes, int n_in,
                              void* d_out, int out_size)
{
    (void)in_sizes; (void)n_in; (void)out_size;
    const float* x     = (const float*)d_in[0];
    const float* W     = (const float*)d_in[1];
    const float* bias  = (const float*)d_in[2];
    const float* loraB = (const float*)d_in[3];
    const float* loraA = (const float*)d_in[4];
    const float* scale = (const float*)d_in[5];
    float* out = (float*)d_out;

    pack_x<<<(int)((size_t)M_TOK * K_IN / 1024), 256>>>(x);
    pack_w<<<(int)((size_t)N_OUT * K_IN / 1024), 256>>>(W, loraB, loraA, scale);

    cudaFuncSetAttribute(lora_mma_gemm,
                         cudaFuncAttributeMaxDynamicSharedMemorySize, SMEM_TOTAL);
    lora_mma_gemm<<<GRID_M * GRID_N, NTHREADS, SMEM_TOTAL>>>(bias, out);
}

// round 17
// speedup vs baseline: 1.0897x; 1.0861x over previous
#include <cuda_runtime.h>
#include <cuda_fp16.h>
#include <cstdint>

#define M_TOK 8192
#define N_OUT 4096
#define K_IN  4096

#define BM 128
#define BN 128
#define BK 32                     // halfwords per chunk (64 bytes/row)
#define NCHUNK (K_IN / BK)        // 128
#define NSTAGE 6
#define T_BYTES (128 * BK * 2)    // 8192 per tile
#define STAGE_BYTES (2 * T_BYTES) // A + B = 16384
#define SMEM_TOTAL (NSTAGE * STAGE_BYTES)   // 98304 -> 2 CTAs/SM

#define NTHREADS 128              // 4 warps, each owns a 64x64 warp tile

#define GRID_M (M_TOK / BM)       // 64
#define GRID_N (N_OUT / BN)       // 32
#define GROUP_M 8

// -------------------- static device scratch (~100 MB) --------------------
__device__ __half g_ax[(size_t)M_TOK * K_IN];  // 67 MB  fp16(x)
__device__ __half g_bw[(size_t)N_OUT * K_IN];  // 33.5 MB fp16(W + s*B@A)

// -------------------- helpers --------------------
static __device__ __forceinline__ uint32_t s2u(const void* p) {
    uint32_t a;
    asm("{ .reg .u64 t; cvta.to.shared.u64 t, %1; cvt.u32.u64 %0, t; }"
        : "=r"(a) : "l"(p));
    return a;
}
// 64-byte-row swizzle (atom = 8 rows x 64B)
#define SWZ64(o) ((o) ^ (((o) >> 3) & 0x30))

static __device__ __forceinline__ void cp16(uint32_t dst, const void* src) {
    asm volatile("cp.async.cg.shared.global [%0], [%1], 16;" :: "r"(dst), "l"(src));
}
static __device__ __forceinline__ void cp_commit() {
    asm volatile("cp.async.commit_group;" ::: "memory");
}

static __device__ __forceinline__ void ldmx4(uint32_t* r, uint32_t addr) {
    asm volatile("ldmatrix.sync.aligned.m8n8.x4.shared.b16 {%0,%1,%2,%3}, [%4];"
                 : "=r"(r[0]), "=r"(r[1]), "=r"(r[2]), "=r"(r[3]) : "r"(addr));
}
static __device__ __forceinline__ void mma16816(float* c, const uint32_t* a,
                                                uint32_t b0, uint32_t b1) {
    asm volatile(
        "mma.sync.aligned.m16n8k16.row.col.f32.f16.f16.f32 "
        "{%0,%1,%2,%3}, {%4,%5,%6,%7}, {%8,%9}, {%0,%1,%2,%3};"
        : "+f"(c[0]), "+f"(c[1]), "+f"(c[2]), "+f"(c[3])
        : "r"(a[0]), "r"(a[1]), "r"(a[2]), "r"(a[3]), "r"(b0), "r"(b1));
}

// ---------- prepass 1: x -> g_ax (single fp16 plane) ----------
__global__ __launch_bounds__(256) void pack_x(const float* __restrict__ x) {
    size_t i = ((size_t)blockIdx.x * 256 + threadIdx.x) * 4;
    float4 v = *(const float4*)(x + i);
    ushort4 h;
    h.x = __half_as_ushort(__float2half_rn(v.x));
    h.y = __half_as_ushort(__float2half_rn(v.y));
    h.z = __half_as_ushort(__float2half_rn(v.z));
    h.w = __half_as_ushort(__float2half_rn(v.w));
    *(ushort4*)((unsigned short*)g_ax + i) = h;
}

// ---------- prepass 2: Wf = W + s*B@A -> g_bw single fp16 plane ----------
__global__ __launch_bounds__(256) void pack_w(
    const float* __restrict__ W, const float* __restrict__ B,
    const float* __restrict__ A, const float* __restrict__ sp)
{
    size_t idx4 = (size_t)blockIdx.x * 256 + threadIdx.x;
    int row = (int)(idx4 >> 10);
    int col = (int)(idx4 & 1023) * 4;
    float s = *sp;

    float4 w = *(const float4*)(W + (size_t)row * K_IN + col);
    float4 acc = make_float4(0.f, 0.f, 0.f, 0.f);
    const float* brow = B + (size_t)row * 16;
    #pragma unroll
    for (int r = 0; r < 16; r++) {
        float b = brow[r];
        float4 a = *(const float4*)(A + (size_t)r * K_IN + col);
        acc.x += b * a.x; acc.y += b * a.y; acc.z += b * a.z; acc.w += b * a.w;
    }
    w.x += s * acc.x; w.y += s * acc.y; w.z += s * acc.z; w.w += s * acc.w;

    ushort4 h;
    h.x = __half_as_ushort(__float2half_rn(w.x));
    h.y = __half_as_ushort(__float2half_rn(w.y));
    h.z = __half_as_ushort(__float2half_rn(w.z));
    h.w = __half_as_ushort(__float2half_rn(w.w));
    *(ushort4*)((unsigned short*)g_bw + (size_t)row * K_IN + col) = h;
}

// -------------------- main GEMM: out = x_h @ w_h^T + bias --------------------
__global__ __launch_bounds__(NTHREADS, 2) void lora_mma_gemm(
    const float* __restrict__ bias, float* __restrict__ out)
{
    extern __shared__ __align__(1024) char smem[];
    const uint32_t sb = s2u(smem);
    const int tid  = threadIdx.x;
    const int lane = tid & 31;
    const int wid  = tid >> 5;
    const int warp_m = wid & 1;       // 2 warps in M -> 64 rows each
    const int warp_n = wid >> 1;      // 2 warps in N -> 64 cols each

    const int bid   = blockIdx.x;
    const int group = bid / (GROUP_M * GRID_N);
    const int inner = bid % (GROUP_M * GRID_N);
    const int bm    = (group * GROUP_M + (inner % GROUP_M)) * BM;
    const int bn    = (inner / GROUP_M) * BN;

    const __half* Ag = g_ax + (size_t)bm * K_IN;
    const __half* Bg = g_bw + (size_t)bn * K_IN;

    const int lrow = lane & 15;
    const int lkb  = (lane >> 4) * 16;   // byte offset within the 32B k-step

    float c[4][8][4];
    #pragma unroll
    for (int i = 0; i < 4; i++)
        #pragma unroll
        for (int j = 0; j < 8; j++)
            #pragma unroll
            for (int q = 0; q < 4; q++) c[i][j][q] = 0.f;

    // stage layout: [A 8K | B 8K], rows are 64 bytes, SW64 swizzle
    auto load_stage = [&](int ch, int st) {
        const uint32_t ab = sb + st * STAGE_BYTES;
        const uint32_t bb = ab + T_BYTES;
        const int k0 = ch * BK;
        #pragma unroll
        for (int i = 0; i < 4; i++) {       // 512 granules of 16B per tile
            int G = tid + i * NTHREADS;
            int r = G >> 2, g = G & 3;
            uint32_t so = SWZ64((uint32_t)(r * 64 + g * 16));
            cp16(ab + so, Ag + (size_t)r * K_IN + k0 + g * 8);
            cp16(bb + so, Bg + (size_t)r * K_IN + k0 + g * 8);
        }
        cp_commit();
    };

    // fragment buffers: buf0 = (ch, ks0), buf1 = (ch, ks1)
    uint32_t ra[2][4][4], rb[2][4][4];
    auto ldfrag = [&](int ch, int ks, int buf) {
        const int st = ch % NSTAGE;
        const uint32_t ab = sb + st * STAGE_BYTES;
        const uint32_t bb = ab + T_BYTES;
        #pragma unroll
        for (int mf = 0; mf < 4; mf++)
            ldmx4(ra[buf][mf],
                  ab + SWZ64((uint32_t)((warp_m * 64 + mf * 16 + lrow) * 64
                                        + ks * 32 + lkb)));
        #pragma unroll
        for (int j = 0; j < 4; j++)
            ldmx4(rb[buf][j],
                  bb + SWZ64((uint32_t)((warp_n * 64 + j * 16 + lrow) * 64
                                        + ks * 32 + lkb)));
    };
    auto do_mmas = [&](int buf) {
        #pragma unroll
        for (int mf = 0; mf < 4; mf++)
            #pragma unroll
            for (int nf = 0; nf < 8; nf++)
                mma16816(c[mf][nf], ra[buf][mf],
                         rb[buf][nf >> 1][nf & 1], rb[buf][nf >> 1][(nf & 1) + 2]);
    };

    // prologue: commit loads for chunks 0..4, warm first fragments
    #pragma unroll
    for (int s = 0; s < NSTAGE - 1; s++) load_stage(s, s);
    asm volatile("cp.async.wait_group 4;" ::: "memory");   // chunk 0 resident
    __syncthreads();
    ldfrag(0, 0, 0);

    for (int ch = 0; ch < NCHUNK; ch++) {
        // committed through ch+4; wait_group 3 -> chunks <= ch+1 resident
        asm volatile("cp.async.wait_group 3;" ::: "memory");
        __syncthreads();   // publish + protect stage (ch-1)%6 for overwrite

        if (ch + NSTAGE - 1 < NCHUNK) {
            const int nc = ch + NSTAGE - 1;
            load_stage(nc, nc % NSTAGE);
        } else cp_commit();   // keep group accounting balanced

        // k-step 0: prefetch (ch, ks1), compute on (ch, ks0)
        ldfrag(ch, 1, 1);
        do_mmas(0);
        // k-step 1: prefetch (ch+1, ks0), compute on (ch, ks1)
        if (ch + 1 < NCHUNK) ldfrag(ch + 1, 0, 0);
        do_mmas(1);
    }

    // -------- epilogue: regs + bias -> gmem --------
    const int tq = lane >> 2, t4 = lane & 3;
    float2 bv[8];
    #pragma unroll
    for (int nf = 0; nf < 8; nf++)
        bv[nf] = *(const float2*)(bias + bn + warp_n * 64 + nf * 8 + t4 * 2);

    #pragma unroll
    for (int mf = 0; mf < 4; mf++) {
        const int r0 = bm + warp_m * 64 + mf * 16 + tq;
        float* o0 = out + (size_t)r0 * N_OUT + bn + warp_n * 64;
        float* o1 = o0 + 8 * N_OUT;
        #pragma unroll
        for (int nf = 0; nf < 8; nf++) {
            const int colo = nf * 8 + t4 * 2;
            *(float2*)(o0 + colo) = make_float2(c[mf][nf][0] + bv[nf].x,
                                                c[mf][nf][1] + bv[nf].y);
            *(float2*)(o1 + colo) = make_float2(c[mf][nf][2] + bv[nf].x,
                                                c[mf][nf][3] + bv[nf].y);
        }
    }
}

// -------------------- launch --------------------
extern "C" void kernel_launch(void* const* d_in, const int* in_sizes, int n_in,
                              void* d_out, int out_size)
{
    (void)in_sizes; (void)n_in; (void)out_size;
    const float* x     = (const float*)d_in[0];
    const float* W     = (const float*)d_in[1];
    const float* bias  = (const float*)d_in[2];
    const float* loraB = (const float*)d_in[3];
    const float* loraA = (const float*)d_in[4];
    const float* scale = (const float*)d_in[5];
    float* out = (float*)d_out;

    pack_x<<<(int)((size_t)M_TOK * K_IN / 1024), 256>>>(x);
    pack_w<<<(int)((size_t)N_OUT * K_IN / 1024), 256>>>(W, loraB, loraA, scale);

    cudaFuncSetAttribute(lora_mma_gemm,
                         cudaFuncAttributeMaxDynamicSharedMemorySize, SMEM_TOTAL);
    lora_mma_gemm<<<GRID_M * GRID_N, NTHREADS, SMEM_TOTAL>>>(bias, out);
}